// round 2
// baseline (speedup 1.0000x reference)
#include <cuda_runtime.h>
#include <math.h>

// Problem constants
#define NB   8
#define CC   256
#define HH   64
#define WW   64
#define LL   4096          // HH*WW
#define GG   8
#define KK   9
#define CG   32            // CC/GG
#define MTOT 32768         // NB*LL
#define OMC  216           // GG*KK*3

// Scratch (static device globals — allowed; no runtime allocation)
__device__ float g_value[(size_t)MTOT * CC];   // (n, l, c)   value projection
__device__ float g_omin [(size_t)MTOT * CC];   // (n, c, l)   depthwise conv out
__device__ float g_om   [(size_t)MTOT * OMC];  // (n, l, 216) offsets+masks
__device__ float g_out2 [(size_t)MTOT * CC];   // (n, l, c)   sampled*mask

// ---------------------------------------------------------------------------
// Depthwise 3x3 conv, SAME zero pad.  out (n,c,l) = b[c] + sum w[c,ky,kx]*x[...]
// ---------------------------------------------------------------------------
__global__ void dwconv_kernel(const float* __restrict__ x,
                              const float* __restrict__ w,
                              const float* __restrict__ b)
{
    int idx = blockIdx.x * 256 + threadIdx.x;   // n*C*L + c*L + l
    int l = idx & (LL - 1);
    int c = (idx >> 12) & (CC - 1);
    int yy = l >> 6;
    int xx = l & (WW - 1);
    const float* wp = w + c * 9;
    const float* xp = x + ((size_t)(idx >> 12)) * LL;  // x[n][c] base
    float acc = b[c];
#pragma unroll
    for (int ky = 0; ky < 3; ky++) {
        int y = yy + ky - 1;
        if ((unsigned)y < HH) {
#pragma unroll
            for (int kx = 0; kx < 3; kx++) {
                int xc = xx + kx - 1;
                if ((unsigned)xc < WW)
                    acc = fmaf(wp[ky * 3 + kx], xp[y * WW + xc], acc);
            }
        }
    }
    g_omin[idx] = acc;
}

// ---------------------------------------------------------------------------
// TN GEMM:  C[m, j] = sum_k A(k, m) * B[j, k] + bias[j]
//   A stored (n, k, l):   element (k, m=(n,l)) at A + n*C*L + k*L + l
//   B (Ncols, 256) row-major
//   which == 0 : A = x     -> g_value (row stride 256)
//   which == 1 : A = g_omin-> g_om    (row stride 216)
// 128x128x8 tile, 256 threads, 8x8 per-thread microtile (n-fast store mapping)
// ---------------------------------------------------------------------------
__global__ __launch_bounds__(256, 2)
void gemm_tn(const float* __restrict__ Aext,
             const float* __restrict__ B,
             const float* __restrict__ bias,
             int Ncols, int which)
{
    __shared__ float As[8][128];
    __shared__ float Bs[8][128];

    const float* A  = (which == 0) ? Aext : g_omin;
    float*       Cm = (which == 0) ? g_value : g_om;

    int m0   = blockIdx.x * 128;
    int nimg = m0 >> 12;           // m0 / LL
    int l0   = m0 & (LL - 1);
    const float* Ab = A + (size_t)nimg * (CC * LL) + l0;
    int jt = blockIdx.y * 128;

    int tid = threadIdx.x;
    int tx = tid & 15;             // column direction (n-fast)
    int ty = tid >> 4;             // row direction

    int ka = tid >> 5;             // A-load: row of BK
    int ma = (tid << 2) & 127;     // A-load: col (float4)
    int jb = tid >> 1;             // B-load: row j
    int kb = (tid & 1) << 2;       // B-load: k offset (float4)
    bool bvalid = (jt + jb) < Ncols;
    const float* Bp = B + (size_t)(jt + jb) * CC + kb;

    float acc[8][8];
#pragma unroll
    for (int i = 0; i < 8; i++)
#pragma unroll
        for (int j = 0; j < 8; j++) acc[i][j] = 0.f;

    for (int k0 = 0; k0 < CC; k0 += 8) {
        float4 av = *(const float4*)(Ab + (size_t)(k0 + ka) * LL + ma);
        float4 bv = bvalid ? *(const float4*)(Bp + k0)
                           : make_float4(0.f, 0.f, 0.f, 0.f);
        *(float4*)&As[ka][ma] = av;
        Bs[kb + 0][jb] = bv.x;
        Bs[kb + 1][jb] = bv.y;
        Bs[kb + 2][jb] = bv.z;
        Bs[kb + 3][jb] = bv.w;
        __syncthreads();
#pragma unroll
        for (int k = 0; k < 8; k++) {
            float ra[8], rb[8];
#pragma unroll
            for (int i = 0; i < 8; i++) ra[i] = As[k][ty + i * 16];
#pragma unroll
            for (int j = 0; j < 8; j++) rb[j] = Bs[k][tx + j * 16];
#pragma unroll
            for (int i = 0; i < 8; i++)
#pragma unroll
                for (int j = 0; j < 8; j++)
                    acc[i][j] = fmaf(ra[i], rb[j], acc[i][j]);
        }
        __syncthreads();
    }

    float bb[8];
#pragma unroll
    for (int j = 0; j < 8; j++) {
        int jc = jt + tx + j * 16;
        bb[j] = (jc < Ncols) ? bias[jc] : 0.f;
    }
#pragma unroll
    for (int i = 0; i < 8; i++) {
        int m = m0 + ty + i * 16;
        float* Crow = Cm + (size_t)m * Ncols;
#pragma unroll
        for (int j = 0; j < 8; j++) {
            int jc = jt + tx + j * 16;
            if (jc < Ncols) Crow[jc] = acc[i][j] + bb[j];
        }
    }
}

// ---------------------------------------------------------------------------
// Deformable bilinear sampling + mask reduce.
// One warp per (n, l, g); lane = channel within group.
// reads g_om (n,l,216), g_value (n,l,g,cg); writes g_out2 (n,l,c)
// ---------------------------------------------------------------------------
__global__ void sample_kernel()
{
    int warp = (blockIdx.x * blockDim.x + threadIdx.x) >> 5;
    int lane = threadIdx.x & 31;
    int g  = warp & (GG - 1);
    int nl = warp >> 3;              // n*L + l
    int l  = nl & (LL - 1);
    int yy = l >> 6;
    int xx = l & (WW - 1);

    const float* omp = g_om + (size_t)nl * OMC + g * 27;
    const float* vb  = g_value + (size_t)(nl >> 12) * ((size_t)LL * CC)
                     + g * CG + lane;

    float acc = 0.f;
#pragma unroll
    for (int k = 0; k < KK; k++) {
        float offy = omp[2 * k];
        float offx = omp[2 * k + 1];
        float mk   = omp[18 + k];
        float py = (float)(yy + (k / 3) - 1) + offy;
        float px = (float)(xx + (k % 3) - 1) + offx;
        float y0f = floorf(py);
        float x0f = floorf(px);
        float tyf = py - y0f;
        float txf = px - x0f;
        int y0 = (int)y0f;
        int x0 = (int)x0f;

        float s = 0.f;
#pragma unroll
        for (int dy = 0; dy < 2; dy++) {
#pragma unroll
            for (int dx = 0; dx < 2; dx++) {
                int yi = y0 + dy;
                int xi = x0 + dx;
                float wgt = (dy ? tyf : (1.f - tyf)) * (dx ? txf : (1.f - txf));
                if (yi >= 0 && yi < HH && xi >= 0 && xi < WW)
                    s = fmaf(wgt, vb[(size_t)(yi * WW + xi) * CC], s);
            }
        }
        acc = fmaf(mk, s, acc);
    }
    g_out2[(size_t)nl * CC + g * CG + lane] = acc;
}

// ---------------------------------------------------------------------------
// NT GEMM (output projection):  out[n, j, l] = sum_k g_out2[m, k] * op_w[j, k]
// A = g_out2 (M,256) row-major; store transposed to NCHW d_out.
// m-fast thread mapping for coalesced NCHW stores.
// ---------------------------------------------------------------------------
__global__ __launch_bounds__(256, 2)
void gemm_nt_out(const float* __restrict__ B, float* __restrict__ Out)
{
    __shared__ float As[8][128];
    __shared__ float Bs[8][128];

    int m0 = blockIdx.x * 128;
    int jt = blockIdx.y * 128;
    int tid = threadIdx.x;
    int tx = tid & 15;             // m direction (fast for stores)
    int ty = tid >> 4;             // column direction

    int rrow = tid >> 1;           // load: row index (m or j)
    int kk4  = (tid & 1) << 2;     // load: k offset
    const float* Ap = g_out2 + (size_t)(m0 + rrow) * CC + kk4;
    const float* Bp = B       + (size_t)(jt + rrow) * CC + kk4;

    float acc[8][8];
#pragma unroll
    for (int i = 0; i < 8; i++)
#pragma unroll
        for (int j = 0; j < 8; j++) acc[i][j] = 0.f;

    for (int k0 = 0; k0 < CC; k0 += 8) {
        float4 av = *(const float4*)(Ap + k0);
        float4 bv = *(const float4*)(Bp + k0);
        As[kk4 + 0][rrow] = av.x;
        As[kk4 + 1][rrow] = av.y;
        As[kk4 + 2][rrow] = av.z;
        As[kk4 + 3][rrow] = av.w;
        Bs[kk4 + 0][rrow] = bv.x;
        Bs[kk4 + 1][rrow] = bv.y;
        Bs[kk4 + 2][rrow] = bv.z;
        Bs[kk4 + 3][rrow] = bv.w;
        __syncthreads();
#pragma unroll
        for (int k = 0; k < 8; k++) {
            float ra[8], rb[8];
#pragma unroll
            for (int i = 0; i < 8; i++) ra[i] = As[k][tx + i * 16];
#pragma unroll
            for (int j = 0; j < 8; j++) rb[j] = Bs[k][ty + j * 16];
#pragma unroll
            for (int i = 0; i < 8; i++)
#pragma unroll
                for (int j = 0; j < 8; j++)
                    acc[i][j] = fmaf(ra[i], rb[j], acc[i][j]);
        }
        __syncthreads();
    }

    int nimg = m0 >> 12;
    int l0   = m0 & (LL - 1);
    float* Ob = Out + (size_t)nimg * (CC * LL);
#pragma unroll
    for (int i = 0; i < 8; i++) {
        int lloc = l0 + tx + i * 16;
#pragma unroll
        for (int j = 0; j < 8; j++) {
            int jc = jt + ty + j * 16;
            Ob[(size_t)jc * LL + lloc] = acc[i][j];
        }
    }
}

// ---------------------------------------------------------------------------
extern "C" void kernel_launch(void* const* d_in, const int* in_sizes, int n_in,
                              void* d_out, int out_size)
{
    const float* x    = (const float*)d_in[0];
    const float* dw_w = (const float*)d_in[1];
    const float* dw_b = (const float*)d_in[2];
    const float* om_w = (const float*)d_in[3];
    const float* om_b = (const float*)d_in[4];
    const float* vp_w = (const float*)d_in[5];
    const float* vp_b = (const float*)d_in[6];
    const float* op_w = (const float*)d_in[7];
    float* out = (float*)d_out;

    // 1. depthwise conv  -> g_omin
    dwconv_kernel<<<(NB * CC * LL) / 256, 256>>>(x, dw_w, dw_b);

    // 2a. offset/mask GEMM  g_omin @ om_w^T + om_b -> g_om  (216 cols)
    gemm_tn<<<dim3(MTOT / 128, 2), 256>>>(nullptr, om_w, om_b, OMC, 1);

    // 2b. value projection  x @ vp_w^T + vp_b -> g_value  (256 cols)
    gemm_tn<<<dim3(MTOT / 128, 2), 256>>>(x, vp_w, vp_b, CC, 0);

    // 3. deformable sampling -> g_out2
    sample_kernel<<<(MTOT * GG) / 8, 256>>>();

    // 4. output projection g_out2 @ op_w^T -> d_out (NCHW)
    gemm_nt_out<<<dim3(MTOT / 128, 2), 256>>>(op_w, out);
}

// round 4
// speedup vs baseline: 3.2780x; 3.2780x over previous
#include <cuda_runtime.h>
#include <cuda_bf16.h>
#include <math.h>
#include <stdint.h>

#define NB 8
#define CC 256
#define HH 64
#define WW 64
#define LL 4096
#define MTOT 32768
#define OMC 216

typedef unsigned short u16;

__device__ float g_omin [(size_t)MTOT * CC];   // dwconv out (n,c,l) fp32
__device__ float g_value[(size_t)MTOT * CC];   // value proj (m,c) fp32
__device__ float g_om   [(size_t)MTOT * 256];  // offsets+masks, pitch 256
__device__ u16 g_xhi[(size_t)MTOT * CC], g_xlo[(size_t)MTOT * CC];   // x  (m,k) bf16
__device__ u16 g_dhi[(size_t)MTOT * CC], g_dlo[(size_t)MTOT * CC];   // dw (m,k) bf16
__device__ u16 g_shi[(size_t)MTOT * CC], g_slo[(size_t)MTOT * CC];   // sampled (m,k) bf16
__device__ u16 g_bhi[3 * 65536], g_blo[3 * 65536];                   // weights (j,k) bf16

// ---- helpers ----
__device__ __forceinline__ uint32_t smem_u32(const void* p) {
    uint32_t a;
    asm("{ .reg .u64 t; cvta.to.shared.u64 t, %1; cvt.u32.u64 %0, t; }" : "=r"(a) : "l"(p));
    return a;
}
#define CPA(sa, ga) asm volatile("cp.async.cg.shared.global [%0], [%1], 16;" :: "r"(sa), "l"(ga))
#define CPC()       asm volatile("cp.async.commit_group;")
#define CPW(n)      asm volatile("cp.async.wait_group %0;" :: "n"(n))

__device__ __forceinline__ void ldx4(uint32_t* r, uint32_t a) {
    asm volatile("ldmatrix.sync.aligned.m8n8.x4.shared.b16 {%0,%1,%2,%3}, [%4];"
                 : "=r"(r[0]), "=r"(r[1]), "=r"(r[2]), "=r"(r[3]) : "r"(a));
}
__device__ __forceinline__ void mma16816(float* d, const uint32_t* a, const uint32_t* b) {
    asm volatile("mma.sync.aligned.m16n8k16.row.col.f32.bf16.bf16.f32 "
                 "{%0,%1,%2,%3},{%4,%5,%6,%7},{%8,%9},{%0,%1,%2,%3};"
                 : "+f"(d[0]), "+f"(d[1]), "+f"(d[2]), "+f"(d[3])
                 : "r"(a[0]), "r"(a[1]), "r"(a[2]), "r"(a[3]), "r"(b[0]), "r"(b[1]));
}
__device__ __forceinline__ void bsplit(float v, u16& h, u16& l) {
    __nv_bfloat16 hb = __float2bfloat16(v);
    __nv_bfloat16 lb = __float2bfloat16(v - __bfloat162float(hb));
    h = *(u16*)&hb; l = *(u16*)&lb;
}

// ---- weight split: om_w (pad 256), vp_w, op_w -> g_bhi/g_blo ----
__global__ void wsplit_kernel(const float* __restrict__ om_w, const float* __restrict__ vp_w,
                              const float* __restrict__ op_w)
{
    int idx = blockIdx.x * 256 + threadIdx.x;      // < 3*65536
    int w = idx >> 16, j = (idx >> 8) & 255, k = idx & 255;
    float v = 0.f;
    if (w == 0)      { if (j < OMC) v = om_w[j * 256 + k]; }
    else if (w == 1) v = vp_w[j * 256 + k];
    else             v = op_w[j * 256 + k];
    u16 h, l; bsplit(v, h, l);
    g_bhi[idx] = h; g_blo[idx] = l;
}

// ---- depthwise 3x3 conv -> g_omin (n,c,l) ----
__global__ void dwconv_kernel(const float* __restrict__ x, const float* __restrict__ w,
                              const float* __restrict__ b)
{
    int idx = blockIdx.x * 256 + threadIdx.x;
    int l = idx & (LL - 1);
    int c = (idx >> 12) & (CC - 1);
    int yy = l >> 6, xx = l & 63;
    const float* wp = w + c * 9;
    const float* xp = x + ((size_t)(idx >> 12)) * LL;
    float acc = b[c];
#pragma unroll
    for (int ky = 0; ky < 3; ky++) {
        int y = yy + ky - 1;
        if ((unsigned)y < HH)
#pragma unroll
            for (int kx = 0; kx < 3; kx++) {
                int xc = xx + kx - 1;
                if ((unsigned)xc < WW) acc = fmaf(wp[ky * 3 + kx], xp[y * WW + xc], acc);
            }
    }
    g_omin[idx] = acc;
}

// ---- transpose (n,C,L)->(m,k) + bf16 split. sel0: x->g_xhi/lo ; sel1: g_omin->g_dhi/lo ----
__global__ void convsplit_kernel(const float* __restrict__ xin, int sel)
{
    __shared__ float t[32][33];
    const float* in = sel ? (const float*)g_omin : xin;
    u16* oh = sel ? g_dhi : g_xhi;
    u16* ol = sel ? g_dlo : g_xlo;
    int n = blockIdx.z, c0 = blockIdx.y * 32, l0 = blockIdx.x * 32;
    int tx = threadIdx.x, ty = threadIdx.y;
    const float* ip = in + ((size_t)n * CC + c0) * LL + l0;
#pragma unroll
    for (int i = 0; i < 4; i++) t[ty + 8 * i][tx] = ip[(size_t)(ty + 8 * i) * LL + tx];
    __syncthreads();
    size_t ob = ((size_t)n * LL + l0) * CC + c0;
#pragma unroll
    for (int i = 0; i < 4; i++) {
        float v = t[tx][ty + 8 * i];
        u16 h, l; bsplit(v, h, l);
        oh[ob + (size_t)(ty + 8 * i) * CC + tx] = h;
        ol[ob + (size_t)(ty + 8 * i) * CC + tx] = l;
    }
}

// ---- bf16x3 HMMA GEMM: C[m,j] = sum_k A[m,k]*W[j,k] (+bias) ----
// CTA 128x128, 8 warps (2m x 4n), k-step 32, double-buffered cp.async.
#define STG 32768
#define GEMM_SMEM 67584

__global__ __launch_bounds__(256, 1)
void gemm_mma(int asel, int wsel, const float* __restrict__ bias, int Ncols,
              int omode, float* __restrict__ outp)
{
    extern __shared__ char smem[];
    uint32_t sb = smem_u32(smem);
    int tid = threadIdx.x, lane = tid & 31, wid = tid >> 5;
    int warpm = wid >> 2, warpn = wid & 3;
    int m0 = blockIdx.x * 128, ntile = blockIdx.y * 128;

    const u16* Ahi = (asel == 0) ? g_xhi : ((asel == 1) ? g_dhi : g_shi);
    const u16* Alo = (asel == 0) ? g_xlo : ((asel == 1) ? g_dlo : g_slo);
    const u16* Bhi = g_bhi + wsel * 65536;
    const u16* Blo = g_blo + wsel * 65536;

    // cp.async mapping: thread -> (row, k-half)
    int crow = tid >> 1, chalf = tid & 1;
    uint32_t csel = (crow >> 1) & 3;
    uint32_t ssw0 = (((uint32_t)chalf * 2 + 0) ^ csel) * 16;
    uint32_t ssw1 = (((uint32_t)chalf * 2 + 1) ^ csel) * 16;
    const u16* gA0 = Ahi + (size_t)(m0 + crow) * 256 + chalf * 16;
    const u16* gA1 = Alo + (size_t)(m0 + crow) * 256 + chalf * 16;
    const u16* gB0 = Bhi + (size_t)(ntile + crow) * 256 + chalf * 16;
    const u16* gB1 = Blo + (size_t)(ntile + crow) * 256 + chalf * 16;

    auto issue = [&](int s, int kc) {
        uint32_t b0 = sb + s * STG + (uint32_t)crow * 64;
        const u16* p;
        p = gA0 + kc * 32; CPA(b0 + ssw0, p);          CPA(b0 + ssw1, p + 8);
        p = gA1 + kc * 32; CPA(b0 + 8192 + ssw0, p);   CPA(b0 + 8192 + ssw1, p + 8);
        p = gB0 + kc * 32; CPA(b0 + 16384 + ssw0, p);  CPA(b0 + 16384 + ssw1, p + 8);
        p = gB1 + kc * 32; CPA(b0 + 24576 + ssw0, p);  CPA(b0 + 24576 + ssw1, p + 8);
        CPC();
    };

    // ldmatrix lane mapping
    int rA = warpm * 64 + (lane & 15);
    uint32_t cbA = (uint32_t)(lane >> 4);
    uint32_t selA = ((uint32_t)rA >> 1) & 3;
    int rB = warpn * 32 + ((lane >> 4) << 3) + (lane & 7);
    uint32_t cbB = (uint32_t)((lane >> 3) & 1);
    uint32_t selB = ((uint32_t)rB >> 1) & 3;

    float acc[4][4][4];
#pragma unroll
    for (int a = 0; a < 4; a++)
#pragma unroll
        for (int b = 0; b < 4; b++)
#pragma unroll
            for (int c = 0; c < 4; c++) acc[a][b][c] = 0.f;

    issue(0, 0);
    issue(1, 1);

    for (int kc = 0; kc < 8; kc++) {
        if (kc < 7) CPW(1); else CPW(0);
        __syncthreads();
        int s = kc & 1;
        uint32_t stg = sb + s * STG;
#pragma unroll
        for (int kk = 0; kk < 2; kk++) {
            uint32_t ah[4][4], al[4][4], bh[4][2], bl[4][2];
#pragma unroll
            for (int mb = 0; mb < 4; mb++) {
                uint32_t a = stg + (uint32_t)(rA + mb * 16) * 64 + (((kk * 2 + cbA) ^ selA) * 16);
                ldx4(ah[mb], a);
                ldx4(al[mb], a + 8192);
            }
#pragma unroll
            for (int p = 0; p < 2; p++) {
                uint32_t a = stg + 16384 + (uint32_t)(rB + p * 16) * 64 + (((kk * 2 + cbB) ^ selB) * 16);
                uint32_t r[4];
                ldx4(r, a);
                bh[2 * p][0] = r[0]; bh[2 * p][1] = r[1];
                bh[2 * p + 1][0] = r[2]; bh[2 * p + 1][1] = r[3];
                ldx4(r, a + 8192);
                bl[2 * p][0] = r[0]; bl[2 * p][1] = r[1];
                bl[2 * p + 1][0] = r[2]; bl[2 * p + 1][1] = r[3];
            }
#pragma unroll
            for (int mb = 0; mb < 4; mb++)
#pragma unroll
                for (int nb = 0; nb < 4; nb++) {
                    mma16816(acc[mb][nb], ah[mb], bh[nb]);
                    mma16816(acc[mb][nb], ah[mb], bl[nb]);
                    mma16816(acc[mb][nb], al[mb], bh[nb]);
                }
        }
        __syncthreads();
        if (kc + 2 < 8) issue(s, kc + 2);
    }

    if (omode < 2) {
        float* Cb = omode ? g_om : g_value;
#pragma unroll
        for (int mb = 0; mb < 4; mb++) {
            int m = m0 + warpm * 64 + mb * 16 + (lane >> 2);
            float* cr = Cb + (size_t)m * 256;
#pragma unroll
            for (int nb = 0; nb < 4; nb++) {
                int j = ntile + warpn * 32 + nb * 8 + (lane & 3) * 2;
                if (j < Ncols) {
                    float b0 = bias[j], b1 = bias[j + 1];
                    float2 v0 = make_float2(acc[mb][nb][0] + b0, acc[mb][nb][1] + b1);
                    float2 v1 = make_float2(acc[mb][nb][2] + b0, acc[mb][nb][3] + b1);
                    *(float2*)(cr + j) = v0;
                    *(float2*)(cr + 2048 + j) = v1;   // row m+8
                }
            }
        }
    } else {
        // transpose through smem, coalesced NCHW stores
        float* ts = (float*)smem;
#pragma unroll
        for (int mb = 0; mb < 4; mb++) {
            int r = warpm * 64 + mb * 16 + (lane >> 2);
#pragma unroll
            for (int nb = 0; nb < 4; nb++) {
                int j = warpn * 32 + nb * 8 + (lane & 3) * 2;
                ts[j * 132 + r]           = acc[mb][nb][0];
                ts[(j + 1) * 132 + r]     = acc[mb][nb][1];
                ts[j * 132 + r + 8]       = acc[mb][nb][2];
                ts[(j + 1) * 132 + r + 8] = acc[mb][nb][3];
            }
        }
        __syncthreads();
        int nimg = m0 >> 12, l0 = m0 & 4095;
        float* Ob = outp + (size_t)nimg * (CC * LL) + l0 + lane * 4;
        int j0 = tid >> 5;
#pragma unroll
        for (int it = 0; it < 16; it++) {
            int j = j0 + it * 8;
            float4 v = *(float4*)(ts + j * 132 + lane * 4);
            *(float4*)(Ob + (size_t)(ntile + j) * LL) = v;
        }
    }
}

// ---- deformable sampling: thread = (nl, g, 4 channels); emits bf16 hi/lo ----
__global__ void sample_kernel()
{
    int t = blockIdx.x * 256 + threadIdx.x;
    int q = t & 7, g = (t >> 3) & 7, nl = t >> 6;
    int l = nl & (LL - 1);
    int yy = l >> 6, xx = l & 63;
    const float* omp = g_om + (size_t)nl * 256 + g * 27;
    const float* vb  = g_value + (size_t)(nl >> 12) * ((size_t)LL * CC) + g * 32 + q * 4;

    float4 acc = make_float4(0.f, 0.f, 0.f, 0.f);
#pragma unroll
    for (int k = 0; k < 9; k++) {
        float py = (float)(yy + (k / 3) - 1) + omp[2 * k];
        float px = (float)(xx + (k % 3) - 1) + omp[2 * k + 1];
        float mk = omp[18 + k];
        float y0f = floorf(py), x0f = floorf(px);
        float ty = py - y0f, tx = px - x0f;
        int y0 = (int)y0f, x0 = (int)x0f;
        float4 s = make_float4(0.f, 0.f, 0.f, 0.f);
#pragma unroll
        for (int dy = 0; dy < 2; dy++)
#pragma unroll
            for (int dx = 0; dx < 2; dx++) {
                int yi = y0 + dy, xi = x0 + dx;
                if (yi >= 0 && yi < HH && xi >= 0 && xi < WW) {
                    float wgt = (dy ? ty : 1.f - ty) * (dx ? tx : 1.f - tx);
                    float4 v = *(const float4*)(vb + (size_t)(yi * WW + xi) * CC);
                    s.x = fmaf(wgt, v.x, s.x); s.y = fmaf(wgt, v.y, s.y);
                    s.z = fmaf(wgt, v.z, s.z); s.w = fmaf(wgt, v.w, s.w);
                }
            }
        acc.x = fmaf(mk, s.x, acc.x); acc.y = fmaf(mk, s.y, acc.y);
        acc.z = fmaf(mk, s.z, acc.z); acc.w = fmaf(mk, s.w, acc.w);
    }
    size_t ob = (size_t)nl * 256 + g * 32 + q * 4;
    ushort4 h, l4;
    bsplit(acc.x, h.x, l4.x); bsplit(acc.y, h.y, l4.y);
    bsplit(acc.z, h.z, l4.z); bsplit(acc.w, h.w, l4.w);
    *(ushort4*)(g_shi + ob) = h;
    *(ushort4*)(g_slo + ob) = l4;
}

// ---------------------------------------------------------------------------
extern "C" void kernel_launch(void* const* d_in, const int* in_sizes, int n_in,
                              void* d_out, int out_size)
{
    const float* x    = (const float*)d_in[0];
    const float* dw_w = (const float*)d_in[1];
    const float* dw_b = (const float*)d_in[2];
    const float* om_w = (const float*)d_in[3];
    const float* om_b = (const float*)d_in[4];
    const float* vp_w = (const float*)d_in[5];
    const float* vp_b = (const float*)d_in[6];
    const float* op_w = (const float*)d_in[7];
    float* out = (float*)d_out;

    cudaFuncSetAttribute(gemm_mma, cudaFuncAttributeMaxDynamicSharedMemorySize, GEMM_SMEM);

    wsplit_kernel<<<768, 256>>>(om_w, vp_w, op_w);
    convsplit_kernel<<<dim3(128, 8, NB), dim3(32, 8)>>>(x, 0);        // x -> g_xhi/lo
    dwconv_kernel<<<(NB * CC * LL) / 256, 256>>>(x, dw_w, dw_b);      // -> g_omin
    convsplit_kernel<<<dim3(128, 8, NB), dim3(32, 8)>>>(nullptr, 1);  // -> g_dhi/lo

    gemm_mma<<<dim3(256, 2), 256, GEMM_SMEM>>>(1, 0, om_b, OMC, 1, nullptr);  // -> g_om
    gemm_mma<<<dim3(256, 2), 256, GEMM_SMEM>>>(0, 1, vp_b, 256, 0, nullptr);  // -> g_value
    sample_kernel<<<(MTOT * 64) / 256, 256>>>();                               // -> g_shi/lo
    gemm_mma<<<dim3(256, 2), 256, GEMM_SMEM>>>(2, 2, nullptr, 256, 2, out);    // -> d_out
}

// round 6
// speedup vs baseline: 4.0771x; 1.2438x over previous
#include <cuda_runtime.h>
#include <cuda_fp16.h>
#include <math.h>
#include <stdint.h>

#define NB 8
#define CC 256
#define HH 64
#define WW 64
#define LL 4096
#define MTOT 32768
#define OMC 216

typedef unsigned short u16;

__device__ float g_value[(size_t)MTOT * CC];   // value proj (m,c) fp32
__device__ float g_om   [(size_t)MTOT * 256];  // offsets+masks, pitch 256
__device__ u16 g_xhi[(size_t)MTOT * CC], g_xlo[(size_t)MTOT * CC];   // x  (m,k) fp16 hi/lo
__device__ u16 g_dhi[(size_t)MTOT * CC], g_dlo[(size_t)MTOT * CC];   // dwconv (m,k)
__device__ u16 g_shi[(size_t)MTOT * CC], g_slo[(size_t)MTOT * CC];   // sampled (m,k)
__device__ u16 g_bh [3 * 65536];                                     // weights hi (j,k)

// ---- helpers ----
__device__ __forceinline__ uint32_t smem_u32(const void* p) {
    uint32_t a;
    asm("{ .reg .u64 t; cvta.to.shared.u64 t, %1; cvt.u32.u64 %0, t; }" : "=r"(a) : "l"(p));
    return a;
}
#define CPA(sa, ga) asm volatile("cp.async.cg.shared.global [%0], [%1], 16;" :: "r"(sa), "l"(ga))
#define CPC()       asm volatile("cp.async.commit_group;")
#define CPW(n)      asm volatile("cp.async.wait_group %0;" :: "n"(n))

__device__ __forceinline__ void ldx4(uint32_t* r, uint32_t a) {
    asm volatile("ldmatrix.sync.aligned.m8n8.x4.shared.b16 {%0,%1,%2,%3}, [%4];"
                 : "=r"(r[0]), "=r"(r[1]), "=r"(r[2]), "=r"(r[3]) : "r"(a));
}
__device__ __forceinline__ void mma16816(float* d, const uint32_t* a, const uint32_t* b) {
    asm volatile("mma.sync.aligned.m16n8k16.row.col.f32.f16.f16.f32 "
                 "{%0,%1,%2,%3},{%4,%5,%6,%7},{%8,%9},{%0,%1,%2,%3};"
                 : "+f"(d[0]), "+f"(d[1]), "+f"(d[2]), "+f"(d[3])
                 : "r"(a[0]), "r"(a[1]), "r"(a[2]), "r"(a[3]), "r"(b[0]), "r"(b[1]));
}
__device__ __forceinline__ void hsplit(float v, u16& h, u16& l) {
    __half hb = __float2half_rn(v);
    __half lb = __float2half_rn(v - __half2float(hb));
    h = *(u16*)&hb; l = *(u16*)&lb;
}

// ---- weight fp16 round: om_w (pad 256), vp_w, op_w -> g_bh ----
__global__ void wsplit_kernel(const float* __restrict__ om_w, const float* __restrict__ vp_w,
                              const float* __restrict__ op_w)
{
    int idx = blockIdx.x * 256 + threadIdx.x;
    int w = idx >> 16, j = (idx >> 8) & 255, k = idx & 255;
    float v = 0.f;
    if (w == 0)      { if (j < OMC) v = om_w[j * 256 + k]; }
    else if (w == 1) v = vp_w[j * 256 + k];
    else             v = op_w[j * 256 + k];
    __half hb = __float2half_rn(v);
    g_bh[idx] = *(u16*)&hb;
}

// ---- x: transpose (n,C,L)->(m,k) + fp16 split ----
__global__ void xsplit_kernel(const float* __restrict__ x)
{
    __shared__ float t[32][33];
    int n = blockIdx.z, c0 = blockIdx.y * 32, l0 = blockIdx.x * 32;
    int tx = threadIdx.x, ty = threadIdx.y;
    const float* ip = x + ((size_t)n * CC + c0) * LL + l0;
#pragma unroll
    for (int i = 0; i < 4; i++) t[ty + 8 * i][tx] = ip[(size_t)(ty + 8 * i) * LL + tx];
    __syncthreads();
    size_t ob = ((size_t)n * LL + l0) * CC + c0;
#pragma unroll
    for (int i = 0; i < 4; i++) {
        u16 h, l; hsplit(t[tx][ty + 8 * i], h, l);
        g_xhi[ob + (size_t)(ty + 8 * i) * CC + tx] = h;
        g_xlo[ob + (size_t)(ty + 8 * i) * CC + tx] = l;
    }
}

// ---- fused depthwise 3x3 conv + transpose + fp16 split -> g_dhi/g_dlo (m,k) ----
__global__ void dwsplit_kernel(const float* __restrict__ x, const float* __restrict__ w,
                               const float* __restrict__ b)
{
    __shared__ float t[32][33];
    int n = blockIdx.z, c0 = blockIdx.y * 32, l0 = blockIdx.x * 32;
    int tx = threadIdx.x, ty = threadIdx.y;
    int l = l0 + tx;
    int yy = l >> 6, xx = l & 63;
#pragma unroll
    for (int i = 0; i < 4; i++) {
        int c = c0 + ty + 8 * i;
        const float* xp = x + ((size_t)n * CC + c) * LL;
        const float* wp = w + c * 9;
        float acc = b[c];
#pragma unroll
        for (int ky = 0; ky < 3; ky++) {
            int y = yy + ky - 1;
            if ((unsigned)y < HH)
#pragma unroll
                for (int kx = 0; kx < 3; kx++) {
                    int xc = xx + kx - 1;
                    if ((unsigned)xc < WW) acc = fmaf(wp[ky * 3 + kx], xp[y * WW + xc], acc);
                }
        }
        t[ty + 8 * i][tx] = acc;
    }
    __syncthreads();
    size_t ob = ((size_t)n * LL + l0) * CC + c0;
#pragma unroll
    for (int i = 0; i < 4; i++) {
        u16 h, lo; hsplit(t[tx][ty + 8 * i], h, lo);
        g_dhi[ob + (size_t)(ty + 8 * i) * CC + tx] = h;
        g_dlo[ob + (size_t)(ty + 8 * i) * CC + tx] = lo;
    }
}

// ---- fp16 2-term HMMA GEMM: C[m,j] = sum_k A[m,k]*Wh[j,k] (+bias) ----
// CTA 128x128, 8 warps (2m x 4n), k-step 32, 3-stage cp.async pipeline.
#define STG3 24576
#define GEMM_SMEM 73728

__global__ __launch_bounds__(256, 1)
void gemm_mma(int asel, int wsel, const float* __restrict__ bias, int Ncols,
              int omode, float* __restrict__ outp)
{
    extern __shared__ char smem[];
    uint32_t sb = smem_u32(smem);
    int tid = threadIdx.x, lane = tid & 31, wid = tid >> 5;
    int warpm = wid >> 2, warpn = wid & 3;
    int m0 = blockIdx.x * 128, ntile = blockIdx.y * 128;

    const u16* Ahi = (asel == 0) ? g_xhi : ((asel == 1) ? g_dhi : g_shi);
    const u16* Alo = (asel == 0) ? g_xlo : ((asel == 1) ? g_dlo : g_slo);
    const u16* Bh  = g_bh + wsel * 65536;

    int crow = tid >> 1, chalf = tid & 1;
    uint32_t csel = (crow >> 1) & 3;
    uint32_t ssw0 = (((uint32_t)chalf * 2 + 0) ^ csel) * 16;
    uint32_t ssw1 = (((uint32_t)chalf * 2 + 1) ^ csel) * 16;
    const u16* gA0 = Ahi + (size_t)(m0 + crow) * 256 + chalf * 16;
    const u16* gA1 = Alo + (size_t)(m0 + crow) * 256 + chalf * 16;
    const u16* gB0 = Bh  + (size_t)(ntile + crow) * 256 + chalf * 16;

    auto issue = [&](int s, int kc) {
        uint32_t b0 = sb + s * STG3 + (uint32_t)crow * 64;
        const u16* p;
        p = gA0 + kc * 32; CPA(b0 + ssw0, p);         CPA(b0 + ssw1, p + 8);
        p = gA1 + kc * 32; CPA(b0 + 8192 + ssw0, p);  CPA(b0 + 8192 + ssw1, p + 8);
        p = gB0 + kc * 32; CPA(b0 + 16384 + ssw0, p); CPA(b0 + 16384 + ssw1, p + 8);
        CPC();
    };

    int rA = warpm * 64 + (lane & 15);
    uint32_t cbA = (uint32_t)(lane >> 4);
    uint32_t selA = ((uint32_t)rA >> 1) & 3;
    int rB = warpn * 32 + ((lane >> 4) << 3) + (lane & 7);
    uint32_t cbB = (uint32_t)((lane >> 3) & 1);
    uint32_t selB = ((uint32_t)rB >> 1) & 3;

    float acc[4][4][4];
#pragma unroll
    for (int a = 0; a < 4; a++)
#pragma unroll
        for (int b = 0; b < 4; b++)
#pragma unroll
            for (int c = 0; c < 4; c++) acc[a][b][c] = 0.f;

    issue(0, 0);
    issue(1, 1);

    for (int kc = 0; kc < 8; kc++) {
        if (kc < 7) CPW(1); else CPW(0);
        __syncthreads();
        int s = kc % 3;
        if (kc + 2 < 8) issue((kc + 2) % 3, kc + 2);
        uint32_t stg = sb + s * STG3;
#pragma unroll
        for (int kk = 0; kk < 2; kk++) {
            uint32_t ah[4][4], al[4][4], bh[4][2];
#pragma unroll
            for (int mb = 0; mb < 4; mb++) {
                uint32_t a = stg + (uint32_t)(rA + mb * 16) * 64 + (((kk * 2 + cbA) ^ selA) * 16);
                ldx4(ah[mb], a);
                ldx4(al[mb], a + 8192);
            }
#pragma unroll
            for (int p = 0; p < 2; p++) {
                uint32_t a = stg + 16384 + (uint32_t)(rB + p * 16) * 64 + (((kk * 2 + cbB) ^ selB) * 16);
                uint32_t r[4];
                ldx4(r, a);
                bh[2 * p][0] = r[0]; bh[2 * p][1] = r[1];
                bh[2 * p + 1][0] = r[2]; bh[2 * p + 1][1] = r[3];
            }
#pragma unroll
            for (int mb = 0; mb < 4; mb++)
#pragma unroll
                for (int nb = 0; nb < 4; nb++) {
                    mma16816(acc[mb][nb], ah[mb], bh[nb]);
                    mma16816(acc[mb][nb], al[mb], bh[nb]);
                }
        }
    }
    __syncthreads();

    if (omode < 2) {
        float* Cb = omode ? g_om : g_value;
#pragma unroll
        for (int mb = 0; mb < 4; mb++) {
            int m = m0 + warpm * 64 + mb * 16 + (lane >> 2);
            float* cr = Cb + (size_t)m * 256;
#pragma unroll
            for (int nb = 0; nb < 4; nb++) {
                int j = ntile + warpn * 32 + nb * 8 + (lane & 3) * 2;
                if (j < Ncols) {
                    float b0 = bias[j], b1 = bias[j + 1];
                    *(float2*)(cr + j) = make_float2(acc[mb][nb][0] + b0, acc[mb][nb][1] + b1);
                    *(float2*)(cr + 2048 + j) = make_float2(acc[mb][nb][2] + b0, acc[mb][nb][3] + b1);
                }
            }
        }
    } else {
        float* ts = (float*)smem;
#pragma unroll
        for (int mb = 0; mb < 4; mb++) {
            int r = warpm * 64 + mb * 16 + (lane >> 2);
#pragma unroll
            for (int nb = 0; nb < 4; nb++) {
                int j = warpn * 32 + nb * 8 + (lane & 3) * 2;
                ts[j * 132 + r]           = acc[mb][nb][0];
                ts[(j + 1) * 132 + r]     = acc[mb][nb][1];
                ts[j * 132 + r + 8]       = acc[mb][nb][2];
                ts[(j + 1) * 132 + r + 8] = acc[mb][nb][3];
            }
        }
        __syncthreads();
        int nimg = m0 >> 12, l0 = m0 & 4095;
        float* Ob = outp + (size_t)nimg * (CC * LL) + l0 + lane * 4;
        int j0 = tid >> 5;
#pragma unroll
        for (int it = 0; it < 16; it++) {
            int j = j0 + it * 8;
            float4 v = *(float4*)(ts + j * 132 + lane * 4);
            *(float4*)(Ob + (size_t)(ntile + j) * LL) = v;
        }
    }
}

// ---- deformable sampling: thread = (nl, g, 8 channels); emits fp16 hi/lo ----
__global__ void sample_kernel()
{
    int t = blockIdx.x * 256 + threadIdx.x;
    int q = t & 3, g = (t >> 2) & 7, nl = t >> 5;
    int l = nl & (LL - 1);
    int yy = l >> 6, xx = l & 63;
    const float* omp = g_om + (size_t)nl * 256 + g * 27;
    const float* vb  = g_value + (size_t)(nl >> 12) * ((size_t)LL * CC) + g * 32 + q * 8;

    float acc[8];
#pragma unroll
    for (int i = 0; i < 8; i++) acc[i] = 0.f;
#pragma unroll
    for (int k = 0; k < 9; k++) {
        float py = (float)(yy + (k / 3) - 1) + omp[2 * k];
        float px = (float)(xx + (k % 3) - 1) + omp[2 * k + 1];
        float mk = omp[18 + k];
        float y0f = floorf(py), x0f = floorf(px);
        float ty = py - y0f, tx = px - x0f;
        int y0 = (int)y0f, x0 = (int)x0f;
        float s[8];
#pragma unroll
        for (int i = 0; i < 8; i++) s[i] = 0.f;
#pragma unroll
        for (int dy = 0; dy < 2; dy++)
#pragma unroll
            for (int dx = 0; dx < 2; dx++) {
                int yi = y0 + dy, xi = x0 + dx;
                if (yi >= 0 && yi < HH && xi >= 0 && xi < WW) {
                    float wgt = (dy ? ty : 1.f - ty) * (dx ? tx : 1.f - tx);
                    const float* vp = vb + (size_t)(yi * WW + xi) * CC;
                    float4 v0 = *(const float4*)vp;
                    float4 v1 = *(const float4*)(vp + 4);
                    s[0] = fmaf(wgt, v0.x, s[0]); s[1] = fmaf(wgt, v0.y, s[1]);
                    s[2] = fmaf(wgt, v0.z, s[2]); s[3] = fmaf(wgt, v0.w, s[3]);
                    s[4] = fmaf(wgt, v1.x, s[4]); s[5] = fmaf(wgt, v1.y, s[5]);
                    s[6] = fmaf(wgt, v1.z, s[6]); s[7] = fmaf(wgt, v1.w, s[7]);
                }
            }
#pragma unroll
        for (int i = 0; i < 8; i++) acc[i] = fmaf(mk, s[i], acc[i]);
    }
    size_t ob = (size_t)nl * 256 + g * 32 + q * 8;
    ushort4 h0, h1, l0, l1;
    hsplit(acc[0], h0.x, l0.x); hsplit(acc[1], h0.y, l0.y);
    hsplit(acc[2], h0.z, l0.z); hsplit(acc[3], h0.w, l0.w);
    hsplit(acc[4], h1.x, l1.x); hsplit(acc[5], h1.y, l1.y);
    hsplit(acc[6], h1.z, l1.z); hsplit(acc[7], h1.w, l1.w);
    *(ushort4*)(g_shi + ob) = h0; *(ushort4*)(g_shi + ob + 4) = h1;
    *(ushort4*)(g_slo + ob) = l0; *(ushort4*)(g_slo + ob + 4) = l1;
}

// ---------------------------------------------------------------------------
extern "C" void kernel_launch(void* const* d_in, const int* in_sizes, int n_in,
                              void* d_out, int out_size)
{
    const float* x    = (const float*)d_in[0];
    const float* dw_w = (const float*)d_in[1];
    const float* dw_b = (const float*)d_in[2];
    const float* om_w = (const float*)d_in[3];
    const float* om_b = (const float*)d_in[4];
    const float* vp_w = (const float*)d_in[5];
    const float* vp_b = (const float*)d_in[6];
    const float* op_w = (const float*)d_in[7];
    float* out = (float*)d_out;

    cudaFuncSetAttribute(gemm_mma, cudaFuncAttributeMaxDynamicSharedMemorySize, GEMM_SMEM);

    wsplit_kernel<<<768, 256>>>(om_w, vp_w, op_w);
    xsplit_kernel<<<dim3(128, 8, NB), dim3(32, 8)>>>(x);                // x -> g_xhi/lo
    dwsplit_kernel<<<dim3(128, 8, NB), dim3(32, 8)>>>(x, dw_w, dw_b);   // -> g_dhi/lo

    gemm_mma<<<dim3(256, 2), 256, GEMM_SMEM>>>(1, 0, om_b, OMC, 1, nullptr);  // -> g_om
    gemm_mma<<<dim3(256, 2), 256, GEMM_SMEM>>>(0, 1, vp_b, 256, 0, nullptr);  // -> g_value
    sample_kernel<<<(MTOT * 32) / 256, 256>>>();                               // -> g_shi/lo
    gemm_mma<<<dim3(256, 2), 256, GEMM_SMEM>>>(2, 2, nullptr, 256, 2, out);    // -> d_out
}